// round 6
// baseline (speedup 1.0000x reference)
#include <cuda_runtime.h>

#define NTOK 4096
#define NP1  4097
#define THREADS 512
#define BUFW 4100                 // u32 per stream buffer (off<=3 + 4096), mult of 4
#define SMEM_BYTES (3 * BUFW * 4)

extern __shared__ unsigned sbuf_all[];

__device__ __forceinline__ float lo_f(unsigned w) { return (float)(unsigned short)(w & 0xFFFFu); }
__device__ __forceinline__ float hi_f(unsigned w) { return (float)(unsigned short)(w >> 16); }

__device__ __forceinline__ float compL(const unsigned* __restrict__ buf, int off, int j,
                                       int cnt, float eos, float pad)
{ return j < cnt ? lo_f(buf[j + off]) : (j == cnt ? eos : pad); }

__device__ __forceinline__ float compH(const unsigned* __restrict__ buf, int off, int j,
                                       int cnt, float eos, float pad)
{ return j < cnt ? hi_f(buf[j + off]) : (j == cnt ? eos : pad); }

// Write content row (low halfwords) and position row (high halfwords) of one
// stream in a single pass. All chunk loads are aligned LDS.128; regions are
// precomputed so the hot loops have no classification branches.
__device__ __forceinline__ void write_pair(float* __restrict__ dstC, float* __restrict__ dstP,
                                           const unsigned* __restrict__ buf, int off, int cnt,
                                           float eosC, float padC, float eosP, float padP,
                                           int tid, int h)
{
    if (tid < h) {
        dstC[tid] = compL(buf, off, tid, cnt, eosC, padC);
        dstP[tid] = compH(buf, off, tid, cnt, eosP, padP);
    }
    const int nv = (NP1 - h) >> 2;
    const uint4* __restrict__ b4 = (const uint4*)buf + ((h + off) >> 2);
    float4* __restrict__ c4 = (float4*)(dstC + h);
    float4* __restrict__ p4 = (float4*)(dstP + h);

    int i_c = (cnt >= h) ? ((cnt - h) >> 2) : 0;  if (i_c > nv) i_c = nv;
    int i_p = (cnt >= h) ? (i_c + 1) : 0;         if (i_p > nv) i_p = nv;

    // pure-content chunks
#pragma unroll 2
    for (int i = tid; i < i_c; i += THREADS) {
        const uint4 w = b4[i];
        c4[i] = make_float4(lo_f(w.x), lo_f(w.y), lo_f(w.z), lo_f(w.w));
        p4[i] = make_float4(hi_f(w.x), hi_f(w.y), hi_f(w.z), hi_f(w.w));
    }
    // boundary chunk (at most one)
    if (tid == 0) {
        for (int i = i_c; i < i_p; i++) {
            const int s = h + i * 4;
            c4[i] = make_float4(compL(buf, off, s,     cnt, eosC, padC),
                                compL(buf, off, s + 1, cnt, eosC, padC),
                                compL(buf, off, s + 2, cnt, eosC, padC),
                                compL(buf, off, s + 3, cnt, eosC, padC));
            p4[i] = make_float4(compH(buf, off, s,     cnt, eosP, padP),
                                compH(buf, off, s + 1, cnt, eosP, padP),
                                compH(buf, off, s + 2, cnt, eosP, padP),
                                compH(buf, off, s + 3, cnt, eosP, padP));
        }
    }
    // pure-pad chunks
    const float4 pc = make_float4(padC, padC, padC, padC);
    const float4 pp = make_float4(padP, padP, padP, padP);
#pragma unroll 2
    for (int i = i_p + tid; i < nv; i += THREADS) { c4[i] = pc; p4[i] = pp; }
    // tail scalars
    const int base = h + nv * 4;
    for (int j = base + tid; j < NP1; j += THREADS) {
        dstC[j] = compL(buf, off, j, cnt, eosC, padC);
        dstP[j] = compH(buf, off, j, cnt, eosP, padP);
    }
}

__device__ __forceinline__ void write_const3(float* __restrict__ d0, float* __restrict__ d1,
                                             float* __restrict__ d2, int tid, int h)
{
    if (tid < h) { d0[tid] = 0.0f; d1[tid] = 1.0f; d2[tid] = 2.0f; }
    const int nv = (NP1 - h) >> 2;
    float4* __restrict__ a4 = (float4*)(d0 + h);
    float4* __restrict__ b4 = (float4*)(d1 + h);
    float4* __restrict__ c4 = (float4*)(d2 + h);
    const float4 z = make_float4(0.f, 0.f, 0.f, 0.f);
    const float4 o = make_float4(1.f, 1.f, 1.f, 1.f);
    const float4 t = make_float4(2.f, 2.f, 2.f, 2.f);
#pragma unroll 2
    for (int i = tid; i < nv; i += THREADS) { a4[i] = z; b4[i] = o; c4[i] = t; }
    const int base = h + nv * 4;
    for (int j = base + tid; j < NP1; j += THREADS) { d0[j] = 0.f; d1[j] = 1.f; d2[j] = 2.f; }
}

__global__ __launch_bounds__(THREADS)
void permute_kernel(const int* __restrict__ indices,
                    const int* __restrict__ grains,
                    float* __restrict__ out,
                    long long M)
{
    __shared__ unsigned wsum[16];
    unsigned* __restrict__ s0 = sbuf_all;
    unsigned* __restrict__ s1 = sbuf_all + BUFW;
    unsigned* __restrict__ s2 = sbuf_all + 2 * BUFW;

    const int b    = blockIdx.x;
    const int tid  = threadIdx.x;
    const int lane = tid & 31;
    const int warp = tid >> 5;

    // ---- load 8 tokens per thread (contiguous chunk -> stability) ----
    const int4* iv = (const int4*)(indices + (long long)b * NTOK);
    const int4* gv = (const int4*)(grains  + (long long)b * NTOK);
    int4 ia = iv[tid * 2], ib = iv[tid * 2 + 1];
    int4 ga = gv[tid * 2], gb = gv[tid * 2 + 1];
    int v[8] = {ia.x, ia.y, ia.z, ia.w, ib.x, ib.y, ib.z, ib.w};
    int g[8] = {ga.x, ga.y, ga.z, ga.w, gb.x, gb.y, gb.z, gb.w};

    // ---- packed local counts: c0 in [0:16), c1 in [16:32) ----
    unsigned packed = 0;
#pragma unroll
    for (int i = 0; i < 8; i++)
        packed += (g[i] == 0) ? 1u : ((g[i] == 1) ? 0x10000u : 0u);

    // ---- block inclusive scan of packed u32 ----
    unsigned p = packed;
#pragma unroll
    for (int d = 1; d < 32; d <<= 1) {
        unsigned t = __shfl_up_sync(0xffffffffu, p, d);
        if (lane >= d) p += t;
    }
    if (lane == 31) wsum[warp] = p;
    __syncthreads();
    if (warp == 0 && lane < 16) {
        unsigned x = wsum[lane];
#pragma unroll
        for (int d = 1; d < 16; d <<= 1) {
            unsigned t = __shfl_up_sync(0x0000ffffu, x, d);
            if (lane >= d) x += t;
        }
        wsum[lane] = x;
    }
    __syncthreads();
    const unsigned excl  = p - packed + (warp ? wsum[warp - 1] : 0u);
    const unsigned total = wsum[15];

    const int e0 = (int)(excl & 0xFFFFu), e1 = (int)(excl >> 16);
    const int c0 = (int)(total & 0xFFFFu), c1 = (int)(total >> 16);
    const int c2 = NTOK - c0 - c1;

    // ---- output row bases; shared head offset h (same for all 9 rows) ----
    const long long rb = (long long)b * NP1;
    float* __restrict__ cc = out + 0 * M + rb;
    const int h   = (int)((0u - ((unsigned)(size_t)cc >> 2)) & 3u);
    const int off = (4 - h) & 3;   // smem offset so chunk s=h+4i is 16B-aligned

    // ---- stable scatter of packed (pos<<16 | content), one STS each ----
    int q0 = e0 + off;
    int q1 = e1 + off;
    int q2 = (tid * 8 - e0 - e1) + off;
    const int t0 = tid * 8;
#pragma unroll
    for (int i = 0; i < 8; i++) {
        const int gi = g[i];
        const unsigned w = (unsigned)v[i] | ((unsigned)(t0 + i) << 16);
        if (gi == 0)      s0[q0++] = w;
        else if (gi == 1) s1[q1++] = w;
        else              s2[q2++] = w;
    }
    __syncthreads();

    // ---- fused coalesced output ----
    write_pair(cc,              out + 3 * M + rb, s0, off, c0,
               1025.f, 1024.f, 129.f, 128.f, tid, h);
    write_pair(out + 1 * M + rb, out + 4 * M + rb, s1, off, c1,
               1025.f, 1024.f, 257.f, 256.f, tid, h);
    write_pair(out + 2 * M + rb, out + 5 * M + rb, s2, off, c2,
               1025.f, 1024.f, 1025.f, 1024.f, tid, h);
    write_const3(out + 6 * M + rb, out + 7 * M + rb, out + 8 * M + rb, tid, h);
}

extern "C" void kernel_launch(void* const* d_in, const int* in_sizes, int n_in,
                              void* d_out, int out_size)
{
    const int* indices = (const int*)d_in[0];
    const int* grains  = (const int*)d_in[1];
    const int rows = in_sizes[0] / NTOK;            // 512
    const long long M = (long long)out_size / 9;    // elements per output tensor
    cudaFuncSetAttribute(permute_kernel, cudaFuncAttributeMaxDynamicSharedMemorySize, SMEM_BYTES);
    permute_kernel<<<rows, THREADS, SMEM_BYTES>>>(indices, grains, (float*)d_out, M);
}